// round 8
// baseline (speedup 1.0000x reference)
#include <cuda_runtime.h>

// TemporalPSPGate: state_t = ALPHA*state_{t-1} + x_t ; out_t = x_t * sigmoid(state_t)
// x [T=16, B=16, H=8, N=256, D=64] fp32. Memory-bound: 256 MiB traffic.
// R5: sigmoid via single-MUFU tanh identity (issue% 50->17).
// R6: kill wave quantization. Was grid=2048 @ 6 CTA/SM -> 2.31 waves; partial
//     3rd wave ran at 31% machine width (matches DRAM 71.5%). Now 4 cols/thread,
//     1024 CTAs x 128 thr = single fully-resident wave (7/6 CTAs per SM, 1.2%
//     imbalance). 4 independent cols/timestep = natural MLP=4, no prefetch bufs.

#define TT 16
#define SPATIAL4 ((16 * 8 * 256 * 64) / 4)   // 524,288 float4 columns
#define CPT 4                                 // columns per thread
#define NTHREADS (SPATIAL4 / CPT)             // 131,072
#define CSTRIDE (SPATIAL4 / CPT)              // column stride between a thread's cols

__device__ __forceinline__ float tanh_approx(float s) {
    float r;
    asm("tanh.approx.f32 %0, %1;" : "=f"(r) : "f"(s));
    return r;
}

__global__ __launch_bounds__(128, 7) void psp_gate_kernel(
    const float4* __restrict__ x, float4* __restrict__ out)
{
    const int gid = blockIdx.x * blockDim.x + threadIdx.x;   // 0 .. NTHREADS-1
    const float alpha = 0.60653065971263342360f;             // exp(-1/2)

    const float4* xp = x + gid;
    float4*       op = out + gid;

    float4 st[CPT];
    #pragma unroll
    for (int c = 0; c < CPT; c++) st[c] = make_float4(0.f, 0.f, 0.f, 0.f);

    #pragma unroll
    for (int t = 0; t < TT; t++) {
        // 4 independent LDG.128 per iteration (c-offsets are 2 MiB apart:
        // fit the LDG immediate field; single pointer increment per t).
        float4 xv[CPT];
        #pragma unroll
        for (int c = 0; c < CPT; c++) xv[c] = __ldcs(xp + c * CSTRIDE);

        #pragma unroll
        for (int c = 0; c < CPT; c++) {
            st[c].x = fmaf(alpha, st[c].x, xv[c].x);
            st[c].y = fmaf(alpha, st[c].y, xv[c].y);
            st[c].z = fmaf(alpha, st[c].z, xv[c].z);
            st[c].w = fmaf(alpha, st[c].w, xv[c].w);

            // sigmoid(s) = 0.5*tanh(0.5*s) + 0.5 ; out = x*sigmoid
            float hx = 0.5f * xv[c].x;
            float hy = 0.5f * xv[c].y;
            float hz = 0.5f * xv[c].z;
            float hw = 0.5f * xv[c].w;

            float4 ov;
            ov.x = fmaf(hx, tanh_approx(0.5f * st[c].x), hx);
            ov.y = fmaf(hy, tanh_approx(0.5f * st[c].y), hy);
            ov.z = fmaf(hz, tanh_approx(0.5f * st[c].z), hz);
            ov.w = fmaf(hw, tanh_approx(0.5f * st[c].w), hw);

            __stcs(op + c * CSTRIDE, ov);
        }

        xp += SPATIAL4;
        op += SPATIAL4;
    }
}

extern "C" void kernel_launch(void* const* d_in, const int* in_sizes, int n_in,
                              void* d_out, int out_size) {
    const float4* x = (const float4*)d_in[0];
    float4* out = (float4*)d_out;
    const int threads = 128;
    const int blocks = NTHREADS / threads;    // 1024 — single resident wave
    psp_gate_kernel<<<blocks, threads>>>(x, out);
}